// round 6
// baseline (speedup 1.0000x reference)
#include <cuda_runtime.h>
#include <math.h>

#ifndef M_PI
#define M_PI 3.14159265358979323846
#endif

// Intermediate yr, shape [4][340][256][256] fp32 (~357 MB), device global.
__device__ float g_yr[89128960];
// 1 if quant is all-ones (DCT->quant->IDCT is identity), else 0.
__device__ int g_ones;

typedef unsigned long long ull;

// ---- packed f32x2 helpers (FFMA2 path; ptxas only emits via explicit PTX) ----
__device__ __forceinline__ ull pk(float x, float y) {
    ull r;
    asm("mov.b64 %0, {%1, %2};" : "=l"(r) : "r"(__float_as_int(x)), "r"(__float_as_int(y)));
    return r;
}
__device__ __forceinline__ void fma2(ull& d, ull a, ull b) {
    asm("fma.rn.f32x2 %0, %1, %2, %0;" : "+l"(d) : "l"(a), "l"(b));
}
__device__ __forceinline__ float2 upk(ull v) {
    int lo, hi;
    asm("mov.b64 {%0, %1}, %2;" : "=r"(lo), "=r"(hi) : "l"(v));
    return make_float2(__int_as_float(lo), __int_as_float(hi));
}

// ---------------------------------------------------------------------------
// Flag kernels: detect quant == all-ones (deterministic every launch).
// ---------------------------------------------------------------------------
__global__ void kinit() {
    if (threadIdx.x == 0) g_ones = 1;
}
__global__ void kcheck(const float* __restrict__ quant) {
    int i = blockIdx.x * 256 + threadIdx.x;   // grid 85 x 256 == 21760
    if (quant[i] != 1.0f) atomicExch(&g_ones, 0);
}

// ---------------------------------------------------------------------------
// Fast path kernel A2 (runs when quant == ones): proj_in as register-blocked
// GEMM with packed f32x2. CTA = 4 rows x 64 cols pixel tile, 256 threads,
// 6 chunks of 64 output channels. Thread micro-tile: 8 outputs x 8 pixels.
// Dyn smem: xs[64][256] (64KB) + Wk[64][64] (16KB) = 81920 B.
// ---------------------------------------------------------------------------
__global__ void __launch_bounds__(256, 2) kernA2(
    const float* __restrict__ x, const float* __restrict__ Win)
{
    if (!*(volatile int*)&g_ones) return;

    extern __shared__ float sm[];
    float* xs = sm;            // [c][p], p = r*64 + cc  (4 rows x 64 cols)
    float* Wk = sm + 16384;    // [c][o] transposed chunk

    const int t = threadIdx.x;
    const int b = blockIdx.z;
    const int row0 = blockIdx.y * 4;
    const int col0 = blockIdx.x * 64;

    // Stage x tile: 64 ch x 256 px, vectorized float4.
    {
        const float* xb = x + ((size_t)b << 22);
        #pragma unroll
        for (int k = 0; k < 16; k++) {
            int i = t + k * 256;           // 0..4095 float4 units
            int c = i >> 6, q = i & 63;    // q indexes 4-float groups
            int r = q >> 4, cc = (q & 15) * 4;
            float4 v = *(const float4*)(xb + ((size_t)c * 256 + row0 + r) * 256 + col0 + cc);
            *(float4*)(xs + c * 256 + q * 4) = v;
        }
    }

    const int po = t & 31;   // pixel group: px A = po*4..+3, px B = po*4+128..+3
    const int oo = t >> 5;   // output group: o = o0 + oo*8 + 0..7
    const int rA = po >> 4, cA = (po * 4) & 63;

    for (int o0 = 0; o0 < 340; o0 += 64) {
        __syncthreads();   // xs ready (1st iter) / prev chunk compute done
        #pragma unroll
        for (int k = 0; k < 16; k++) {
            int i = t + k * 256;            // 0..4095
            int c = i >> 6, o = i & 63;
            Wk[i] = (o0 + o < 340) ? Win[(o0 + o) * 64 + c] : 0.0f;
        }
        __syncthreads();

        ull acc[8][4];
        #pragma unroll
        for (int o = 0; o < 8; o++)
            #pragma unroll
            for (int j = 0; j < 4; j++) acc[o][j] = 0ull;

        #pragma unroll 4
        for (int c = 0; c < 64; c++) {
            float4 xa = *(const float4*)(xs + c * 256 + po * 4);
            float4 xb4 = *(const float4*)(xs + c * 256 + po * 4 + 128);
            ull x0 = pk(xa.x, xa.y), x1 = pk(xa.z, xa.w);
            ull x2 = pk(xb4.x, xb4.y), x3 = pk(xb4.z, xb4.w);
            float4 wa = *(const float4*)(Wk + c * 64 + oo * 8);
            float4 wb = *(const float4*)(Wk + c * 64 + oo * 8 + 4);
            float wv[8] = {wa.x, wa.y, wa.z, wa.w, wb.x, wb.y, wb.z, wb.w};
            #pragma unroll
            for (int o = 0; o < 8; o++) {
                ull wd = pk(wv[o], wv[o]);
                fma2(acc[o][0], wd, x0);
                fma2(acc[o][1], wd, x1);
                fma2(acc[o][2], wd, x2);
                fma2(acc[o][3], wd, x3);
            }
        }

        #pragma unroll
        for (int o = 0; o < 8; o++) {
            int og = o0 + oo * 8 + o;
            if (og < 340) {
                float2 p0 = upk(acc[o][0]), p1 = upk(acc[o][1]);
                float2 p2 = upk(acc[o][2]), p3 = upk(acc[o][3]);
                size_t pl = ((size_t)b * 340 + og) * 65536;
                *(float4*)(g_yr + pl + (size_t)(row0 + rA) * 256 + col0 + cA) =
                    make_float4(p0.x, p0.y, p1.x, p1.y);
                *(float4*)(g_yr + pl + (size_t)(row0 + rA + 2) * 256 + col0 + cA) =
                    make_float4(p2.x, p2.y, p3.x, p3.y);
            }
        }
    }
}

// ---------------------------------------------------------------------------
// Fallback kernel A (runs when quant != ones): round-1 fused proj_in + DCT +
// quant + IDCT. Unchanged except the gate.
// ---------------------------------------------------------------------------
__global__ void __launch_bounds__(256, 2) kernA(
    const float* __restrict__ x, const float* __restrict__ Win,
    const float* __restrict__ quant)
{
    if (*(volatile int*)&g_ones) return;

    extern __shared__ float sm[];
    float* xs   = sm;
    float* bufA = sm + 16384;
    float* bufB = sm + 18688;
    float* Wk   = sm + 20992;
    float* qk   = sm + 21504;
    float* Ms   = sm + 22016;

    const int t  = threadIdx.x;
    const int b  = blockIdx.z;
    const int tx = blockIdx.x, ty = blockIdx.y;
    const int lx = t & 15, ly = t >> 4;
    const int gx = tx * 16 + lx, gy = ty * 16 + ly;

    if (t < 64) {
        int i = t >> 3, j = t & 7;
        Ms[t] = (i == 0) ? 0.3535533905932738f
                         : 0.5f * cosf((float)M_PI * (float)(i * (2 * j + 1)) / 16.0f);
    }
    {
        const float* xb = x + ((size_t)b << 22);
        int pofs = gy * 256 + gx;
        #pragma unroll
        for (int c = 0; c < 64; c++)
            xs[c * 256 + t] = xb[c * 65536 + pofs];
    }

    const int ch  = t >> 5;
    const int pat = (t >> 3) & 3;
    const int ln  = t & 7;
    float* pA = bufA + ch * 288 + pat * 72;
    float* pB = bufB + ch * 288 + pat * 72;

    const int patc = ((ly >> 3) << 1) + (lx >> 3);
    const int rr = ly & 7, cc = lx & 7;
    float* convDst = bufA + patc * 72 + rr * 9 + cc;

    for (int o0 = 0; o0 < 340; o0 += 8) {
        #pragma unroll
        for (int r = 0; r < 2; r++) {
            int idx = t + r * 256;
            int c = idx >> 3, o = idx & 7;
            Wk[idx] = (o0 + o < 340) ? Win[(o0 + o) * 64 + c] : 0.0f;
            int o2 = idx >> 6, rc = idx & 63;
            qk[idx] = (o0 + o2 < 340) ? quant[(o0 + o2) * 64 + rc] : 0.0f;
        }
        __syncthreads();

        float acc[8] = {0.f, 0.f, 0.f, 0.f, 0.f, 0.f, 0.f, 0.f};
        #pragma unroll 8
        for (int c = 0; c < 64; c++) {
            float  xv = xs[c * 256 + t];
            float4 w0 = *reinterpret_cast<const float4*>(Wk + c * 8);
            float4 w1 = *reinterpret_cast<const float4*>(Wk + c * 8 + 4);
            acc[0] += w0.x * xv; acc[1] += w0.y * xv;
            acc[2] += w0.z * xv; acc[3] += w0.w * xv;
            acc[4] += w1.x * xv; acc[5] += w1.y * xv;
            acc[6] += w1.z * xv; acc[7] += w1.w * xv;
        }
        #pragma unroll
        for (int o = 0; o < 8; o++) convDst[o * 288] = acc[o];
        __syncthreads();

        float v[8];
        #pragma unroll
        for (int p = 0; p < 8; p++) v[p] = pA[p * 9 + ln];
        #pragma unroll
        for (int i = 0; i < 8; i++) {
            float s = 0.f;
            #pragma unroll
            for (int p = 0; p < 8; p++) s += Ms[i * 8 + p] * v[p];
            pB[i * 9 + ln] = s;
        }
        __syncthreads();

        #pragma unroll
        for (int q = 0; q < 8; q++) v[q] = pB[ln * 9 + q];
        #pragma unroll
        for (int j = 0; j < 8; j++) {
            float s = 0.f;
            #pragma unroll
            for (int q = 0; q < 8; q++) s += v[q] * Ms[j * 8 + q];
            pA[ln * 9 + j] = s * qk[ch * 64 + ln * 8 + j];
        }
        __syncthreads();

        #pragma unroll
        for (int p = 0; p < 8; p++) v[p] = pA[p * 9 + ln];
        #pragma unroll
        for (int i = 0; i < 8; i++) {
            float s = 0.f;
            #pragma unroll
            for (int p = 0; p < 8; p++) s += Ms[p * 8 + i] * v[p];
            pB[i * 9 + ln] = s;
        }
        __syncthreads();

        #pragma unroll
        for (int q = 0; q < 8; q++) v[q] = pB[ln * 9 + q];
        int o = o0 + ch;
        if (o < 340) {
            float r8[8];
            #pragma unroll
            for (int j = 0; j < 8; j++) {
                float s = 0.f;
                #pragma unroll
                for (int q = 0; q < 8; q++) s += v[q] * Ms[q * 8 + j];
                r8[j] = s;
            }
            int py = pat >> 1, px = pat & 1;
            size_t base = (((size_t)b * 340 + o) * 256 +
                           (size_t)(ty * 16 + py * 8 + ln)) * 256 +
                          (size_t)(tx * 16 + px * 8);
            float4* dst = reinterpret_cast<float4*>(g_yr + base);
            dst[0] = make_float4(r8[0], r8[1], r8[2], r8[3]);
            dst[1] = make_float4(r8[4], r8[5], r8[6], r8[7]);
        }
    }
}

// ---------------------------------------------------------------------------
// Kernel B2: fused depthwise 3x3 + exact-GELU gate + proj_out, packed f32x2,
// channel-pair interleaved tiles, double-buffered prefetch.
// Dyn smem (floats): Wo 10880 | pdw 3060 | tb 1296  -> 60944 B.
// ---------------------------------------------------------------------------
__global__ void __launch_bounds__(256, 2) kernB2(
    const float* __restrict__ Wdw, const float* __restrict__ Wout,
    float* __restrict__ out)
{
    extern __shared__ float smB[];
    float*  Wo  = smB;                       // [oh][64], Wout transposed
    float2* pdw = (float2*)(smB + 10880);    // [oh][9]  packed {w1,w2}
    float2* tb  = (float2*)(smB + 13940);    // [2][324] packed {yr1,yr2}

    const int t  = threadIdx.x;
    const int b  = blockIdx.z;
    const int tx = blockIdx.x, ty = blockIdx.y;
    const int lx = t & 15, ly = t >> 4;
    const int gx = tx * 16 + lx, gy = ty * 16 + ly;

    for (int i = t; i < 10880; i += 256)
        Wo[i] = Wout[(i & 63) * 170 + (i >> 6)];
    for (int i = t; i < 1530; i += 256) {
        int oh = i / 9, k = i - oh * 9;
        pdw[i] = make_float2(Wdw[oh * 9 + k], Wdw[(oh + 170) * 9 + k]);
    }

    // Halo load slots: i1 = t (<324 always), i2 = t + 256 (valid t < 68)
    const size_t bbase = (size_t)b * 340 * 65536;
    int r1i = t / 18, c1i = t - r1i * 18;
    int yy1 = ty * 16 + r1i - 1, xx1 = tx * 16 + c1i - 1;
    bool in1 = ((unsigned)yy1 < 256u) && ((unsigned)xx1 < 256u);
    size_t a1 = in1 ? bbase + (size_t)yy1 * 256 + xx1 : bbase;

    int i2 = t + 256;
    int r2i = i2 / 18, c2i = i2 - r2i * 18;
    int yy2 = ty * 16 + r2i - 1, xx2 = tx * 16 + c2i - 1;
    bool hv2 = (t < 68);
    bool in2 = hv2 && ((unsigned)yy2 < 256u) && ((unsigned)xx2 < 256u);
    size_t a2 = in2 ? bbase + (size_t)yy2 * 256 + xx2 : bbase;

    // Prefetch channel 0 pair
    float v1a = in1 ? g_yr[a1] : 0.f;
    float v1b = in1 ? g_yr[a1 + (size_t)170 * 65536] : 0.f;
    float v2a = in2 ? g_yr[a2] : 0.f;
    float v2b = in2 ? g_yr[a2 + (size_t)170 * 65536] : 0.f;

    ull acc[32];
    #pragma unroll
    for (int j = 0; j < 32; j++) acc[j] = 0ull;

    const ull*        pdwu = (const ull*)pdw;
    const ull*        tbu  = (const ull*)tb;
    const ulonglong2* Wo2  = (const ulonglong2*)Wo;

    int cur = 0;
    for (int oh = 0; oh < 170; oh++) {
        tb[cur * 324 + t] = make_float2(v1a, v1b);
        if (hv2) tb[cur * 324 + i2] = make_float2(v2a, v2b);
        __syncthreads();

        if (oh < 169) {   // prefetch next channel pair (overlaps compute)
            size_t o1 = a1 + (size_t)(oh + 1) * 65536;
            size_t o2 = a2 + (size_t)(oh + 1) * 65536;
            v1a = in1 ? g_yr[o1] : 0.f;
            v1b = in1 ? g_yr[o1 + (size_t)170 * 65536] : 0.f;
            v2a = in2 ? g_yr[o2] : 0.f;
            v2b = in2 ? g_yr[o2 + (size_t)170 * 65536] : 0.f;
        }

        // depthwise 3x3 on channel pair (packed)
        ull d2 = 0ull;
        #pragma unroll
        for (int ky = 0; ky < 3; ky++)
            #pragma unroll
            for (int kx = 0; kx < 3; kx++)
                fma2(d2, tbu[cur * 324 + (ly + ky) * 18 + lx + kx],
                         pdwu[oh * 9 + ky * 3 + kx]);
        float2 d = upk(d2);
        float g = 0.5f * d.x * (1.0f + erff(d.x * 0.7071067811865476f)) * d.y;
        ull gg = pk(g, g);

        // proj_out accumulate: 64 outputs as 32 packed pairs
        #pragma unroll
        for (int j4 = 0; j4 < 16; j4++) {
            ulonglong2 w2 = Wo2[oh * 16 + j4];
            fma2(acc[j4 * 2 + 0], gg, w2.x);
            fma2(acc[j4 * 2 + 1], gg, w2.y);
        }
        cur ^= 1;
    }

    size_t obase = ((size_t)b * 64) * 65536 + (size_t)gy * 256 + (size_t)gx;
    #pragma unroll
    for (int j = 0; j < 32; j++) {
        float2 v = upk(acc[j]);
        out[obase + (size_t)(j * 2 + 0) * 65536] = v.x;
        out[obase + (size_t)(j * 2 + 1) * 65536] = v.y;
    }
}

// ---------------------------------------------------------------------------
extern "C" void kernel_launch(void* const* d_in, const int* in_sizes, int n_in,
                              void* d_out, int out_size)
{
    (void)in_sizes; (void)n_in; (void)out_size;
    const float* x     = (const float*)d_in[0];  // [4,64,256,256]
    const float* Win   = (const float*)d_in[1];  // [340,64]
    const float* Wdw   = (const float*)d_in[2];  // [340,1,3,3]
    const float* quant = (const float*)d_in[3];  // [340,1,1,8,8]
    const float* Wout  = (const float*)d_in[4];  // [64,170]
    float* out = (float*)d_out;                  // [4,64,256,256]

    static int attr_done = 0;
    if (!attr_done) {
        cudaFuncSetAttribute(kernA,  cudaFuncAttributeMaxDynamicSharedMemorySize, 88320);
        cudaFuncSetAttribute(kernA2, cudaFuncAttributeMaxDynamicSharedMemorySize, 81920);
        cudaFuncSetAttribute(kernB2, cudaFuncAttributeMaxDynamicSharedMemorySize, 60944);
        attr_done = 1;
    }

    kinit<<<1, 32>>>();
    kcheck<<<85, 256>>>(quant);                       // 85*256 == 21760

    dim3 gOld(16, 16, 4), blk(256);
    kernA<<<gOld, blk, 88320>>>(x, Win, quant);       // runs only if quant != 1

    dim3 gA2(4, 64, 4);
    kernA2<<<gA2, blk, 81920>>>(x, Win);              // runs only if quant == 1

    kernB2<<<gOld, blk, 60944>>>(Wdw, Wout, out);
}

// round 7
// speedup vs baseline: 1.2798x; 1.2798x over previous
#include <cuda_runtime.h>
#include <math.h>
#include <stdint.h>

#ifndef M_PI
#define M_PI 3.14159265358979323846
#endif

// Intermediate yr, shape [4][340][256][256] fp32 (~357 MB), device global.
__device__ float g_yr[89128960];
// 1 if quant is all-ones (DCT->quant->IDCT is identity), else 0.
__device__ int g_ones;

typedef unsigned long long ull;

// ---- packed f32x2 helpers ----
__device__ __forceinline__ ull pk(float x, float y) {
    ull r;
    asm("mov.b64 %0, {%1, %2};" : "=l"(r) : "r"(__float_as_int(x)), "r"(__float_as_int(y)));
    return r;
}
__device__ __forceinline__ void fma2(ull& d, ull a, ull b) {
    asm("fma.rn.f32x2 %0, %1, %2, %0;" : "+l"(d) : "l"(a), "l"(b));
}
__device__ __forceinline__ float2 upk(ull v) {
    int lo, hi;
    asm("mov.b64 {%0, %1}, %2;" : "=r"(lo), "=r"(hi) : "l"(v));
    return make_float2(__int_as_float(lo), __int_as_float(hi));
}

// ---- cp.async helpers ----
__device__ __forceinline__ void cp4(uint32_t dst, uint64_t gsrc, unsigned sz) {
    // 4-byte async copy, zero-fill when sz==0 (halo out-of-bounds)
    asm volatile("cp.async.ca.shared.global [%0], [%1], 4, %2;"
                 :: "r"(dst), "l"(gsrc), "r"(sz));
}
__device__ __forceinline__ void cp_commit() {
    asm volatile("cp.async.commit_group;" ::: "memory");
}
__device__ __forceinline__ void cp_wait1() {
    asm volatile("cp.async.wait_group 1;" ::: "memory");
}
__device__ __forceinline__ uint32_t smem_u32(const void* p) {
    uint32_t a;
    asm("{ .reg .u64 t; cvta.to.shared.u64 t, %1; cvt.u32.u64 %0, t; }"
        : "=r"(a) : "l"(p));
    return a;
}
__device__ __forceinline__ uint64_t gmem_u64(const void* p) {
    uint64_t a;
    asm("cvta.to.global.u64 %0, %1;" : "=l"(a) : "l"(p));
    return a;
}

// ---------------------------------------------------------------------------
// Flag kernels: detect quant == all-ones (deterministic every launch).
// ---------------------------------------------------------------------------
__global__ void kinit() {
    if (threadIdx.x == 0) g_ones = 1;
}
__global__ void kcheck(const float* __restrict__ quant) {
    int i = blockIdx.x * 256 + threadIdx.x;   // grid 85 x 256 == 21760
    if (quant[i] != 1.0f) atomicExch(&g_ones, 0);
}

// ---------------------------------------------------------------------------
// Fast path kernel A2 (quant == ones): proj_in as register-blocked GEMM with
// packed f32x2, weights stored dup-packed (w,w) in smem to kill pack movs.
// CTA = 4x64 pixel tile, 256 threads, 6 chunks of 64 output channels.
// Dyn smem: xs[64][256] (64KB) + Wk2[64][64] ull (32KB) = 98304 B.
// ---------------------------------------------------------------------------
__global__ void __launch_bounds__(256, 2) kernA2(
    const float* __restrict__ x, const float* __restrict__ Win)
{
    if (!*(volatile int*)&g_ones) return;

    extern __shared__ float sm[];
    float* xs  = sm;                       // [c][p]
    ull*   Wk2 = (ull*)(sm + 16384);       // [c][o] dup-packed

    const int t = threadIdx.x;
    const int b = blockIdx.z;
    const int row0 = blockIdx.y * 4;
    const int col0 = blockIdx.x * 64;

    // Stage x tile: 64 ch x 256 px, vectorized float4.
    {
        const float* xb = x + ((size_t)b << 22);
        #pragma unroll
        for (int k = 0; k < 16; k++) {
            int i = t + k * 256;
            int c = i >> 6, q = i & 63;
            int r = q >> 4, cc = (q & 15) * 4;
            float4 v = *(const float4*)(xb + ((size_t)c * 256 + row0 + r) * 256 + col0 + cc);
            *(float4*)(xs + c * 256 + q * 4) = v;
        }
    }

    const int po = t & 31;
    const int oo = t >> 5;
    const int rA = po >> 4, cA = (po * 4) & 63;

    for (int o0 = 0; o0 < 340; o0 += 64) {
        __syncthreads();
        #pragma unroll
        for (int k = 0; k < 16; k++) {
            int i = t + k * 256;
            int c = i >> 6, o = i & 63;
            float w = (o0 + o < 340) ? Win[(o0 + o) * 64 + c] : 0.0f;
            Wk2[i] = pk(w, w);
        }
        __syncthreads();

        ull acc[8][4];
        #pragma unroll
        for (int o = 0; o < 8; o++)
            #pragma unroll
            for (int j = 0; j < 4; j++) acc[o][j] = 0ull;

        #pragma unroll 4
        for (int c = 0; c < 64; c++) {
            float4 xa  = *(const float4*)(xs + c * 256 + po * 4);
            float4 xb4 = *(const float4*)(xs + c * 256 + po * 4 + 128);
            ull x0 = pk(xa.x, xa.y),  x1 = pk(xa.z, xa.w);
            ull x2 = pk(xb4.x, xb4.y), x3 = pk(xb4.z, xb4.w);
            const ulonglong2* wp = (const ulonglong2*)(Wk2 + c * 64 + oo * 8);
            ulonglong2 wA = wp[0], wB = wp[1], wC = wp[2], wD = wp[3];
            ull wv[8] = {wA.x, wA.y, wB.x, wB.y, wC.x, wC.y, wD.x, wD.y};
            #pragma unroll
            for (int o = 0; o < 8; o++) {
                fma2(acc[o][0], wv[o], x0);
                fma2(acc[o][1], wv[o], x1);
                fma2(acc[o][2], wv[o], x2);
                fma2(acc[o][3], wv[o], x3);
            }
        }

        #pragma unroll
        for (int o = 0; o < 8; o++) {
            int og = o0 + oo * 8 + o;
            if (og < 340) {
                float2 p0 = upk(acc[o][0]), p1 = upk(acc[o][1]);
                float2 p2 = upk(acc[o][2]), p3 = upk(acc[o][3]);
                size_t pl = ((size_t)b * 340 + og) * 65536;
                *(float4*)(g_yr + pl + (size_t)(row0 + rA) * 256 + col0 + cA) =
                    make_float4(p0.x, p0.y, p1.x, p1.y);
                *(float4*)(g_yr + pl + (size_t)(row0 + rA + 2) * 256 + col0 + cA) =
                    make_float4(p2.x, p2.y, p3.x, p3.y);
            }
        }
    }
}

// ---------------------------------------------------------------------------
// Fallback kernel A (quant != ones): fused proj_in + DCT + quant + IDCT.
// ---------------------------------------------------------------------------
__global__ void __launch_bounds__(256, 2) kernA(
    const float* __restrict__ x, const float* __restrict__ Win,
    const float* __restrict__ quant)
{
    if (*(volatile int*)&g_ones) return;

    extern __shared__ float sm[];
    float* xs   = sm;
    float* bufA = sm + 16384;
    float* bufB = sm + 18688;
    float* Wk   = sm + 20992;
    float* qk   = sm + 21504;
    float* Ms   = sm + 22016;

    const int t  = threadIdx.x;
    const int b  = blockIdx.z;
    const int tx = blockIdx.x, ty = blockIdx.y;
    const int lx = t & 15, ly = t >> 4;
    const int gx = tx * 16 + lx, gy = ty * 16 + ly;

    if (t < 64) {
        int i = t >> 3, j = t & 7;
        Ms[t] = (i == 0) ? 0.3535533905932738f
                         : 0.5f * cosf((float)M_PI * (float)(i * (2 * j + 1)) / 16.0f);
    }
    {
        const float* xb = x + ((size_t)b << 22);
        int pofs = gy * 256 + gx;
        #pragma unroll
        for (int c = 0; c < 64; c++)
            xs[c * 256 + t] = xb[c * 65536 + pofs];
    }

    const int ch  = t >> 5;
    const int pat = (t >> 3) & 3;
    const int ln  = t & 7;
    float* pA = bufA + ch * 288 + pat * 72;
    float* pB = bufB + ch * 288 + pat * 72;

    const int patc = ((ly >> 3) << 1) + (lx >> 3);
    const int rr = ly & 7, cc = lx & 7;
    float* convDst = bufA + patc * 72 + rr * 9 + cc;

    for (int o0 = 0; o0 < 340; o0 += 8) {
        #pragma unroll
        for (int r = 0; r < 2; r++) {
            int idx = t + r * 256;
            int c = idx >> 3, o = idx & 7;
            Wk[idx] = (o0 + o < 340) ? Win[(o0 + o) * 64 + c] : 0.0f;
            int o2 = idx >> 6, rc = idx & 63;
            qk[idx] = (o0 + o2 < 340) ? quant[(o0 + o2) * 64 + rc] : 0.0f;
        }
        __syncthreads();

        float acc[8] = {0.f, 0.f, 0.f, 0.f, 0.f, 0.f, 0.f, 0.f};
        #pragma unroll 8
        for (int c = 0; c < 64; c++) {
            float  xv = xs[c * 256 + t];
            float4 w0 = *reinterpret_cast<const float4*>(Wk + c * 8);
            float4 w1 = *reinterpret_cast<const float4*>(Wk + c * 8 + 4);
            acc[0] += w0.x * xv; acc[1] += w0.y * xv;
            acc[2] += w0.z * xv; acc[3] += w0.w * xv;
            acc[4] += w1.x * xv; acc[5] += w1.y * xv;
            acc[6] += w1.z * xv; acc[7] += w1.w * xv;
        }
        #pragma unroll
        for (int o = 0; o < 8; o++) convDst[o * 288] = acc[o];
        __syncthreads();

        float v[8];
        #pragma unroll
        for (int p = 0; p < 8; p++) v[p] = pA[p * 9 + ln];
        #pragma unroll
        for (int i = 0; i < 8; i++) {
            float s = 0.f;
            #pragma unroll
            for (int p = 0; p < 8; p++) s += Ms[i * 8 + p] * v[p];
            pB[i * 9 + ln] = s;
        }
        __syncthreads();

        #pragma unroll
        for (int q = 0; q < 8; q++) v[q] = pB[ln * 9 + q];
        #pragma unroll
        for (int j = 0; j < 8; j++) {
            float s = 0.f;
            #pragma unroll
            for (int q = 0; q < 8; q++) s += v[q] * Ms[j * 8 + q];
            pA[ln * 9 + j] = s * qk[ch * 64 + ln * 8 + j];
        }
        __syncthreads();

        #pragma unroll
        for (int p = 0; p < 8; p++) v[p] = pA[p * 9 + ln];
        #pragma unroll
        for (int i = 0; i < 8; i++) {
            float s = 0.f;
            #pragma unroll
            for (int p = 0; p < 8; p++) s += Ms[p * 8 + i] * v[p];
            pB[i * 9 + ln] = s;
        }
        __syncthreads();

        #pragma unroll
        for (int q = 0; q < 8; q++) v[q] = pB[ln * 9 + q];
        int o = o0 + ch;
        if (o < 340) {
            float r8[8];
            #pragma unroll
            for (int j = 0; j < 8; j++) {
                float s = 0.f;
                #pragma unroll
                for (int q = 0; q < 8; q++) s += v[q] * Ms[q * 8 + j];
                r8[j] = s;
            }
            int py = pat >> 1, px = pat & 1;
            size_t base = (((size_t)b * 340 + o) * 256 +
                           (size_t)(ty * 16 + py * 8 + ln)) * 256 +
                          (size_t)(tx * 16 + px * 8);
            float4* dst = reinterpret_cast<float4*>(g_yr + base);
            dst[0] = make_float4(r8[0], r8[1], r8[2], r8[3]);
            dst[1] = make_float4(r8[4], r8[5], r8[6], r8[7]);
        }
    }
}

// ---------------------------------------------------------------------------
// Kernel B3: fused depthwise 3x3 + exact-GELU gate + proj_out.
// 3-stage cp.async pipeline, 2 channel-pairs per barrier round (85 rounds).
// Dyn smem: Wo 43520 | pdw 12240 | tb 3 stages x 2 pairs x 324 f2 = 15552
//   -> 71312 B total.  occ 2.
// ---------------------------------------------------------------------------
__global__ void __launch_bounds__(256, 2) kernB3(
    const float* __restrict__ Wdw, const float* __restrict__ Wout,
    float* __restrict__ out)
{
    extern __shared__ float smB[];
    float*  Wo  = smB;                      // [oh][64]
    float2* pdw = (float2*)(smB + 10880);   // [oh][9]  packed {w1,w2}
    float2* tb  = (float2*)(smB + 13940);   // [3][2][324]

    const int t  = threadIdx.x;
    const int b  = blockIdx.z;
    const int tx = blockIdx.x, ty = blockIdx.y;
    const int lx = t & 15, ly = t >> 4;
    const int gx = tx * 16 + lx, gy = ty * 16 + ly;

    for (int i = t; i < 10880; i += 256)
        Wo[i] = Wout[(i & 63) * 170 + (i >> 6)];
    for (int i = t; i < 1530; i += 256) {
        int oh = i / 9, k = i - oh * 9;
        pdw[i] = make_float2(Wdw[oh * 9 + k], Wdw[(oh + 170) * 9 + k]);
    }

    // Halo slots: slot1 = t (always < 324), slot2 = t + 256 (valid t < 68).
    const size_t bbase = (size_t)b * 340 * 65536;
    int r1i = t / 18, c1i = t - r1i * 18;
    int yy1 = ty * 16 + r1i - 1, xx1 = tx * 16 + c1i - 1;
    bool in1 = ((unsigned)yy1 < 256u) && ((unsigned)xx1 < 256u);
    size_t e1 = in1 ? bbase + (size_t)yy1 * 256 + xx1 : bbase;
    unsigned sz1 = in1 ? 4u : 0u;

    const int i2 = t + 256;
    int r2i = i2 / 18, c2i = i2 - r2i * 18;
    int yy2 = ty * 16 + r2i - 1, xx2 = tx * 16 + c2i - 1;
    const bool hv2 = (t < 68);
    bool in2 = hv2 && ((unsigned)yy2 < 256u) && ((unsigned)xx2 < 256u);
    size_t e2 = in2 ? bbase + (size_t)yy2 * 256 + xx2 : bbase;
    unsigned sz2 = in2 ? 4u : 0u;

    const uint64_t yrg = gmem_u64(g_yr);
    const uint64_t g1 = yrg + e1 * 4;       // byte address, channel 0 plane
    const uint64_t g2 = yrg + e2 * 4;
    const uint32_t tbu32 = smem_u32(tb);
    const uint64_t CH  = 262144ull;          // one channel plane, bytes
    const uint64_t CHB = 170ull * 262144ull; // gate half offset, bytes

    // Round loader: pairs (2r, 2r+1) into stage r%3.
    auto load_round = [&](int r) {
        uint32_t sb = tbu32 + (uint32_t)(r % 3) * 5184u;
        uint64_t s1 = g1 + (uint64_t)(2 * r) * CH;
        // pair 0
        cp4(sb + t * 8u,      s1,       sz1);
        cp4(sb + t * 8u + 4u, s1 + CHB, sz1);
        // pair 1
        cp4(sb + 2592u + t * 8u,      s1 + CH,       sz1);
        cp4(sb + 2592u + t * 8u + 4u, s1 + CH + CHB, sz1);
        if (hv2) {
            uint64_t s2 = g2 + (uint64_t)(2 * r) * CH;
            cp4(sb + i2 * 8u,      s2,       sz2);
            cp4(sb + i2 * 8u + 4u, s2 + CHB, sz2);
            cp4(sb + 2592u + i2 * 8u,      s2 + CH,       sz2);
            cp4(sb + 2592u + i2 * 8u + 4u, s2 + CH + CHB, sz2);
        }
    };

    // Prologue: rounds 0 and 1.
    load_round(0); cp_commit();
    load_round(1); cp_commit();

    ull acc[32];
    #pragma unroll
    for (int j = 0; j < 32; j++) acc[j] = 0ull;

    const ull*        pdwu = (const ull*)pdw;
    const ulonglong2* Wo2  = (const ulonglong2*)Wo;

    for (int r = 0; r < 85; r++) {
        cp_wait1();          // round r's group complete (own thread)
        __syncthreads();     // all threads' round-r data + (iter0) Wo/pdw visible

        if (r + 2 < 85) load_round(r + 2);
        cp_commit();         // always commit (empty group keeps the count)

        const ull* tbs = (const ull*)((const char*)tb + (size_t)(r % 3) * 5184);
        #pragma unroll
        for (int pr = 0; pr < 2; pr++) {
            int oh = 2 * r + pr;
            ull d2 = 0ull;
            #pragma unroll
            for (int ky = 0; ky < 3; ky++)
                #pragma unroll
                for (int kx = 0; kx < 3; kx++)
                    fma2(d2, tbs[pr * 324 + (ly + ky) * 18 + lx + kx],
                             pdwu[oh * 9 + ky * 3 + kx]);
            float2 d = upk(d2);
            float g = 0.5f * d.x * (1.0f + erff(d.x * 0.7071067811865476f)) * d.y;
            ull gg = pk(g, g);
            #pragma unroll
            for (int j4 = 0; j4 < 16; j4++) {
                ulonglong2 w2 = Wo2[oh * 16 + j4];
                fma2(acc[j4 * 2 + 0], gg, w2.x);
                fma2(acc[j4 * 2 + 1], gg, w2.y);
            }
        }
    }

    size_t obase = ((size_t)b * 64) * 65536 + (size_t)gy * 256 + (size_t)gx;
    #pragma unroll
    for (int j = 0; j < 32; j++) {
        float2 v = upk(acc[j]);
        out[obase + (size_t)(j * 2 + 0) * 65536] = v.x;
        out[obase + (size_t)(j * 2 + 1) * 65536] = v.y;
    }
}

// ---------------------------------------------------------------------------
extern "C" void kernel_launch(void* const* d_in, const int* in_sizes, int n_in,
                              void* d_out, int out_size)
{
    (void)in_sizes; (void)n_in; (void)out_size;
    const float* x     = (const float*)d_in[0];  // [4,64,256,256]
    const float* Win   = (const float*)d_in[1];  // [340,64]
    const float* Wdw   = (const float*)d_in[2];  // [340,1,3,3]
    const float* quant = (const float*)d_in[3];  // [340,1,1,8,8]
    const float* Wout  = (const float*)d_in[4];  // [64,170]
    float* out = (float*)d_out;                  // [4,64,256,256]

    static int attr_done = 0;
    if (!attr_done) {
        cudaFuncSetAttribute(kernA,  cudaFuncAttributeMaxDynamicSharedMemorySize, 88320);
        cudaFuncSetAttribute(kernA2, cudaFuncAttributeMaxDynamicSharedMemorySize, 98304);
        cudaFuncSetAttribute(kernB3, cudaFuncAttributeMaxDynamicSharedMemorySize, 71312);
        attr_done = 1;
    }

    kinit<<<1, 32>>>();
    kcheck<<<85, 256>>>(quant);

    dim3 gOld(16, 16, 4), blk(256);
    kernA<<<gOld, blk, 88320>>>(x, Win, quant);   // runs only if quant != 1

    dim3 gA2(4, 64, 4);
    kernA2<<<gA2, blk, 98304>>>(x, Win);          // runs only if quant == 1

    kernB3<<<gOld, blk, 71312>>>(Wdw, Wout, out);
}